// round 2
// baseline (speedup 1.0000x reference)
#include <cuda_runtime.h>
#include <math.h>

// Problem constants (fixed by the reference: N, M, D, Q = 4096, 4096, 4, 4)
#define NROWS 4096
#define MCOLS 4096
#define QMIX  4
#define DDIM  4
#define NFIELD 13   // per (row,q): [0..3]=xs/y, [4..11]=pair trig, [12]=A

// Scratch feature arrays (field-major: [q][field][row]) — 832KB each.
__device__ float g_xfeat[QMIX * NFIELD * NROWS];
__device__ float g_yfeat[QMIX * NFIELD * MCOLS];

__device__ __forceinline__ float ex2f(float x) {
    float y;
    asm("ex2.approx.f32 %0, %1;" : "=f"(y) : "f"(x));
    return y;
}

// ---------------------------------------------------------------------------
// Kernel 1: per-row feature precompute (off the hot path).
//
//   theta_d = 2*pi*mu_qd*r_d.  Pair angles:
//     u1 = th0+th1, u2 = th0-th1, v1 = th2+th3, v2 = th2-th3
//   Identity: prod_d cos(th_d(x)-th_d(y))
//           = 1/4 [cos(u1x-u1y)+cos(u2x-u2y)] [cos(v1x-v1y)+cos(v2x-v2y)]
//   The 1/4 is folded into the x-side trig (scaled by 0.5 per pair).
//
//   Exp part: k_exp = exp2( Ax + Ay + sum_d xs_d * y_d ) with
//     xs_d = 2*(2pi^2)*log2e * v_qd * x_d,   Ax = log2(w_q) - 2pi^2*log2e*sum v x^2
// ---------------------------------------------------------------------------
__global__ void feat_kernel(const float* __restrict__ x, const float* __restrict__ y,
                            const float* __restrict__ lw, const float* __restrict__ mu,
                            const float* __restrict__ lv) {
    int i = blockIdx.x * blockDim.x + threadIdx.x;
    if (i >= NROWS + MCOLS) return;
    const bool isX = (i < NROWS);
    const int n = isX ? i : i - NROWS;
    const float* row = isX ? (x + n * DDIM) : (y + n * DDIM);
    float* out = isX ? g_xfeat : g_yfeat;
    const int L = isX ? NROWS : MCOLS;

    const float TWO_PI = 6.283185307179586f;
    const float C2     = 19.739208802178716f;   // 2*pi^2
    const float LOG2E  = 1.4426950408889634f;

    float r[DDIM];
#pragma unroll
    for (int d = 0; d < DDIM; ++d) r[d] = row[d];

#pragma unroll
    for (int q = 0; q < QMIX; ++q) {
        float th[DDIM];
        float sum = 0.f;
#pragma unroll
        for (int d = 0; d < DDIM; ++d) {
            float v = expf(lv[q * DDIM + d]);
            float m = mu[q * DDIM + d];
            th[d] = TWO_PI * m * r[d];
            out[(q * NFIELD + d) * L + n] = isX ? (2.f * C2 * LOG2E * v * r[d]) : r[d];
            sum += v * r[d] * r[d];
        }
        const float sc = isX ? 0.5f : 1.0f;
        float u1 = th[0] + th[1], u2 = th[0] - th[1];
        float v1 = th[2] + th[3], v2 = th[2] - th[3];
        float s, c;
        sincosf(u1, &s, &c);
        out[(q * NFIELD + 4) * L + n] = sc * c;  out[(q * NFIELD + 5) * L + n] = sc * s;
        sincosf(u2, &s, &c);
        out[(q * NFIELD + 6) * L + n] = sc * c;  out[(q * NFIELD + 7) * L + n] = sc * s;
        sincosf(v1, &s, &c);
        out[(q * NFIELD + 8) * L + n] = sc * c;  out[(q * NFIELD + 9) * L + n] = sc * s;
        sincosf(v2, &s, &c);
        out[(q * NFIELD + 10) * L + n] = sc * c; out[(q * NFIELD + 11) * L + n] = sc * s;

        float A = -C2 * LOG2E * sum;
        if (isX) A += lw[q] * LOG2E;
        out[(q * NFIELD + 12) * L + n] = A;
    }
}

// ---------------------------------------------------------------------------
// Kernel 2: 64x64 output tile per block, 128 threads, 4x8 micro-tile per
// thread processed FULL-WIDTH per q (X-side fields loaded once per q).
// Y trig operands are consumed per 4-column half to bound register liveness
// without re-loading X.
// ---------------------------------------------------------------------------
#define LD4(dst, ptr) do { float4 t4_ = *reinterpret_cast<const float4*>(ptr); \
    (dst)[0] = t4_.x; (dst)[1] = t4_.y; (dst)[2] = t4_.z; (dst)[3] = t4_.w; } while (0)

__global__ void __launch_bounds__(128, 3)
sm_tile_kernel(float* __restrict__ out) {
    __shared__ float XS[QMIX * NFIELD * 64];   // 13312 B
    __shared__ float YS[QMIX * NFIELD * 64];

    const int rowBase = blockIdx.y * 64;
    const int colBase = blockIdx.x * 64;
    const int tid = threadIdx.x;

    // Cooperative smem fill: 52 segments x 16 float4 per side.
    {
        float4* xs4 = reinterpret_cast<float4*>(XS);
        float4* ys4 = reinterpret_cast<float4*>(YS);
        for (int s = tid; s < QMIX * NFIELD * 16; s += 128) {
            const int seg = s >> 4;
            const int j   = s & 15;
            xs4[s] = *reinterpret_cast<const float4*>(&g_xfeat[seg * NROWS + rowBase + j * 4]);
            ys4[s] = *reinterpret_cast<const float4*>(&g_yfeat[seg * MCOLS + colBase + j * 4]);
        }
    }
    __syncthreads();

    const int tx = tid & 7;        // 8 column groups
    const int ty = tid >> 3;       // 16 row groups
    const int r0 = ty * 4;
    const int c0 = tx * 8;

    float acc[4][8];
#pragma unroll
    for (int r = 0; r < 4; ++r)
#pragma unroll
        for (int c = 0; c < 8; ++c) acc[r][c] = 0.f;

#pragma unroll 1
    for (int q = 0; q < QMIX; ++q) {
        const float* Xq = XS + q * NFIELD * 64;
        const float* Yq = YS + q * NFIELD * 64;

        // ---- exponential factor: ev = exp2(Ax + Ay + sum_d xs_d*y_d) ----
        float ax[4], ay[8];
        LD4(ax, Xq + 12 * 64 + r0);
        LD4(ay,     Yq + 12 * 64 + c0);
        LD4(ay + 4, Yq + 12 * 64 + c0 + 4);

        float ev[4][8];
#pragma unroll
        for (int r = 0; r < 4; ++r)
#pragma unroll
            for (int c = 0; c < 8; ++c) ev[r][c] = ax[r] + ay[c];

#pragma unroll
        for (int d = 0; d < 4; ++d) {
            float xs[4], yv[8];
            LD4(xs, Xq + d * 64 + r0);
            LD4(yv,     Yq + d * 64 + c0);
            LD4(yv + 4, Yq + d * 64 + c0 + 4);
#pragma unroll
            for (int r = 0; r < 4; ++r)
#pragma unroll
                for (int c = 0; c < 8; ++c)
                    ev[r][c] = fmaf(xs[r], yv[c], ev[r][c]);
        }
#pragma unroll
        for (int r = 0; r < 4; ++r)
#pragma unroll
            for (int c = 0; c < 8; ++c) ev[r][c] = ex2f(ev[r][c]);

        // ---- t1 = 0.5*[cos(u1x-u1y)+cos(u2x-u2y)]  (0.5 pre-folded into X) ----
        float t[4][8];
        {
            float cu1[4], su1[4], cu2[4], su2[4];
            LD4(cu1, Xq + 4 * 64 + r0);
            LD4(su1, Xq + 5 * 64 + r0);
            LD4(cu2, Xq + 6 * 64 + r0);
            LD4(su2, Xq + 7 * 64 + r0);
#pragma unroll
            for (int h = 0; h < 2; ++h) {
                const int cb = h * 4;
                float yc1[4], ys1[4], yc2[4], ys2[4];
                LD4(yc1, Yq + 4 * 64 + c0 + cb);
                LD4(ys1, Yq + 5 * 64 + c0 + cb);
                LD4(yc2, Yq + 6 * 64 + c0 + cb);
                LD4(ys2, Yq + 7 * 64 + c0 + cb);
#pragma unroll
                for (int r = 0; r < 4; ++r)
#pragma unroll
                    for (int c = 0; c < 4; ++c) {
                        float v = fmaf(cu1[r], yc1[c], su1[r] * ys1[c]);
                        v = fmaf(cu2[r], yc2[c], v);
                        v = fmaf(su2[r], ys2[c], v);
                        t[r][c + cb] = v;
                    }
            }
        }
        // fold t1 into ev, freeing t for reuse
#pragma unroll
        for (int r = 0; r < 4; ++r)
#pragma unroll
            for (int c = 0; c < 8; ++c) ev[r][c] *= t[r][c];

        // ---- t2 = 0.5*[cos(v1x-v1y)+cos(v2x-v2y)], then accumulate ----
        {
            float cv1[4], sv1[4], cv2[4], sv2[4];
            LD4(cv1, Xq + 8 * 64 + r0);
            LD4(sv1, Xq + 9 * 64 + r0);
            LD4(cv2, Xq + 10 * 64 + r0);
            LD4(sv2, Xq + 11 * 64 + r0);
#pragma unroll
            for (int h = 0; h < 2; ++h) {
                const int cb = h * 4;
                float yc1[4], ys1[4], yc2[4], ys2[4];
                LD4(yc1, Yq + 8 * 64 + c0 + cb);
                LD4(ys1, Yq + 9 * 64 + c0 + cb);
                LD4(yc2, Yq + 10 * 64 + c0 + cb);
                LD4(ys2, Yq + 11 * 64 + c0 + cb);
#pragma unroll
                for (int r = 0; r < 4; ++r)
#pragma unroll
                    for (int c = 0; c < 4; ++c) {
                        float v = fmaf(cv1[r], yc1[c], sv1[r] * ys1[c]);
                        v = fmaf(cv2[r], yc2[c], v);
                        v = fmaf(sv2[r], ys2[c], v);
                        acc[r][c + cb] = fmaf(ev[r][c + cb], v, acc[r][c + cb]);
                    }
            }
        }
    }

    // Store 4x8 micro-tile as two float4 per row.
#pragma unroll
    for (int r = 0; r < 4; ++r) {
        const size_t base = (size_t)(rowBase + r0 + r) * MCOLS + colBase + c0;
        float4 v0 = make_float4(acc[r][0], acc[r][1], acc[r][2], acc[r][3]);
        float4 v1 = make_float4(acc[r][4], acc[r][5], acc[r][6], acc[r][7]);
        *reinterpret_cast<float4*>(&out[base])     = v0;
        *reinterpret_cast<float4*>(&out[base + 4]) = v1;
    }
}

extern "C" void kernel_launch(void* const* d_in, const int* in_sizes, int n_in,
                              void* d_out, int out_size) {
    const float* x  = (const float*)d_in[0];
    const float* y  = (const float*)d_in[1];
    const float* lw = (const float*)d_in[2];
    const float* mu = (const float*)d_in[3];
    const float* lv = (const float*)d_in[4];
    float* out = (float*)d_out;

    (void)in_sizes; (void)n_in; (void)out_size;

    feat_kernel<<<(NROWS + MCOLS + 255) / 256, 256>>>(x, y, lw, mu, lv);

    dim3 grid(MCOLS / 64, NROWS / 64);
    sm_tile_kernel<<<grid, 128>>>(out);
}